// round 2
// baseline (speedup 1.0000x reference)
#include <cuda_runtime.h>
#include <stdint.h>

// ModSTDP: bit-exact replication of jax.random (threefry2x32, partitionable
// counter scheme, default in modern JAX) + the 4-branch STDP update.
//
// Scheme assumed: jax_threefry_partitionable = True (JAX >= 0.5 default):
//   split(key, n) fold-like: rk[i] = threefry(key, (0, i)) -> (x0, x1)
//   random_bits 32-bit for element e: x0 ^ x1 of threefry(key, (0, e))
// If rel_err fails, fall back to the original halved-iota scheme next round.

constexpr uint32_t NNEUR = 2048;
constexpr uint32_t NSYN  = 8192;
constexpr uint32_t TOT   = NNEUR * NSYN;   // 16777216 = 2^24

// ---------------- compile-time threefry2x32 (key derivation) ----------------
struct P2 { uint32_t a, b; };

constexpr uint32_t rotl_c(uint32_t x, int r) { return (x << r) | (x >> (32 - r)); }

constexpr P2 tf_c(uint32_t k0, uint32_t k1, uint32_t c0, uint32_t c1) {
  uint32_t k2 = k0 ^ k1 ^ 0x1BD11BDAu;
  uint32_t x0 = c0 + k0, x1 = c1 + k1;
  int RA[4] = {13, 15, 26, 6};
  int RB[4] = {17, 29, 16, 24};
  for (int i = 0; i < 4; i++) { x0 += x1; x1 = rotl_c(x1, RA[i]); x1 ^= x0; }
  x0 += k1; x1 += k2 + 1u;
  for (int i = 0; i < 4; i++) { x0 += x1; x1 = rotl_c(x1, RB[i]); x1 ^= x0; }
  x0 += k2; x1 += k0 + 2u;
  for (int i = 0; i < 4; i++) { x0 += x1; x1 = rotl_c(x1, RA[i]); x1 ^= x0; }
  x0 += k0; x1 += k1 + 3u;
  for (int i = 0; i < 4; i++) { x0 += x1; x1 = rotl_c(x1, RB[i]); x1 ^= x0; }
  x0 += k1; x1 += k2 + 4u;
  for (int i = 0; i < 4; i++) { x0 += x1; x1 = rotl_c(x1, RA[i]); x1 ^= x0; }
  x0 += k2; x1 += k0 + 5u;
  return P2{x0, x1};
}

// master key = jax.random.key(42) -> (0, 42)
// rk[i] = threefry((0,42), (0,i)); field mapping per reference:
// rk0 fplus, rk1 fminus, rk2 ucapture, rk3 uminus, rk4 usearch, rk5 ubackoff,
// rk6 umin1; k7a/k7b/k7c = split(rk7, 3) -> umin2, umin3, umin4.
constexpr P2 RK7_ = tf_c(0u, 42u, 0u, 7u);

constexpr uint32_t RK0a = tf_c(0u, 42u, 0u, 0u).a, RK0b = tf_c(0u, 42u, 0u, 0u).b;
constexpr uint32_t RK1a = tf_c(0u, 42u, 0u, 1u).a, RK1b = tf_c(0u, 42u, 0u, 1u).b;
constexpr uint32_t RK2a = tf_c(0u, 42u, 0u, 2u).a, RK2b = tf_c(0u, 42u, 0u, 2u).b;
constexpr uint32_t RK3a = tf_c(0u, 42u, 0u, 3u).a, RK3b = tf_c(0u, 42u, 0u, 3u).b;
constexpr uint32_t RK4a = tf_c(0u, 42u, 0u, 4u).a, RK4b = tf_c(0u, 42u, 0u, 4u).b;
constexpr uint32_t RK5a = tf_c(0u, 42u, 0u, 5u).a, RK5b = tf_c(0u, 42u, 0u, 5u).b;
constexpr uint32_t RK6a = tf_c(0u, 42u, 0u, 6u).a, RK6b = tf_c(0u, 42u, 0u, 6u).b;
constexpr uint32_t K7Aa = tf_c(RK7_.a, RK7_.b, 0u, 0u).a, K7Ab = tf_c(RK7_.a, RK7_.b, 0u, 0u).b;
constexpr uint32_t K7Ba = tf_c(RK7_.a, RK7_.b, 0u, 1u).a, K7Bb = tf_c(RK7_.a, RK7_.b, 0u, 1u).b;
constexpr uint32_t K7Ca = tf_c(RK7_.a, RK7_.b, 0u, 2u).a, K7Cb = tf_c(RK7_.a, RK7_.b, 0u, 2u).b;

// ---------------- device threefry: bits for element e under key (k0,k1) ----
__device__ __forceinline__ uint32_t tf_bits(uint32_t k0, uint32_t k1, uint32_t e) {
  uint32_t k2 = k0 ^ k1 ^ 0x1BD11BDAu;
  uint32_t x0 = k0;          // lane0 counter = hi(e) = 0
  uint32_t x1 = e + k1;      // lane1 counter = lo(e) = e
#define R_(r) { x0 += x1; x1 = __funnelshift_l(x1, x1, (r)); x1 ^= x0; }
  R_(13) R_(15) R_(26) R_(6)
  x0 += k1; x1 += k2 + 1u;
  R_(17) R_(29) R_(16) R_(24)
  x0 += k2; x1 += k0 + 2u;
  R_(13) R_(15) R_(26) R_(6)
  x0 += k0; x1 += k1 + 3u;
  R_(17) R_(29) R_(16) R_(24)
  x0 += k1; x1 += k2 + 4u;
  R_(13) R_(15) R_(26) R_(6)
  x0 += k2; x1 += k0 + 5u;
#undef R_
  return x0 ^ x1;  // 32-bit partitionable random bits
}

__device__ __forceinline__ float u01f(uint32_t bits) {
  // exact replica of jax uniform: bitcast((bits>>9)|1.0f) - 1.0f
  return __uint_as_float((bits >> 9) | 0x3f800000u) - 1.0f;
}

// ---------------- main kernel --------------------------------------------
__global__ void __launch_bounds__(256) modstdp_kernel(
    const int* __restrict__ ispk,     // [8, N, S] int32 0/1
    const int* __restrict__ ospk,     // [8, N]    int32 0/1
    const float* __restrict__ W,      // [N, S]
    float* __restrict__ out)          // [N, S]
{
  const uint32_t e = blockIdx.x * 256u + threadIdx.x;

  // in_t = 8 - sum_t spikes ; warp-coalesced 4B loads, 8 x 64MB streams
  int s = 0;
#pragma unroll
  for (int t = 0; t < 8; t++) s += __ldg(ispk + (size_t)t * TOT + e);
  const int it = 8 - s;

  // out_t per neuron. n is BLOCK-uniform (256 <= S=8192, blocks never
  // straddle a neuron row) -> these 8 loads are uniform broadcasts.
  const uint32_t n = (blockIdx.x * 256u) >> 13;
  int so = 0;
#pragma unroll
  for (int t = 0; t < 8; t++) so += __ldg(ospk + t * NNEUR + n);
  const int ot = 8 - so;

  const float w = fminf(fmaxf(__ldg(W + e), 0.0f), 8.0f);

  const bool inf = it < 8, ouf = ot < 8;
  // branch: 1 capture(+), 2 minus(-), 3 search(+), 4 backoff(-), 0 none
  const int br = (inf & ouf) ? ((it <= ot) ? 1 : 2)
                             : (inf ? 3 : (ouf ? 4 : 0));
  const bool plus = (br == 1) | (br == 3);

  const unsigned FM = 0xffffffffu;

  // --- draw 1: branch's u-flag. Key is selected PER THREAD (threefry code is
  // field-independent), so all four u-fields cost ONE threefry per element.
  bool u = false;
  if (__any_sync(FM, br != 0)) {
    const uint32_t k0 = (br <= 2) ? ((br == 1) ? RK2a : RK3a)
                                  : ((br == 3) ? RK4a : RK5a);
    const uint32_t k1 = (br <= 2) ? ((br == 1) ? RK2b : RK3b)
                                  : ((br == 3) ? RK4b : RK5b);
    const float th = (br <= 2) ? 0.078125f            // ucapture / uminus 10/128
                               : ((br == 3) ? 0.0078125f   // usearch 1/128
                                            : 0.75f);      // ubackoff 96/128
    u = (u01f(tf_bits(k0, k1, e)) < th) && (br != 0);
  }

  // --- draw 2: fplus/fminus (w-dependent p) only where u == 1 (~8%)
  bool f = false;
  if (__any_sync(FM, u)) {
    const uint32_t k0 = plus ? RK0a : RK1a;
    const uint32_t k1 = plus ? RK0b : RK1b;
    const float wn = w * 0.125f;                      // exact /8
    const float pf = plus ? (wn * (2.0f - wn))        // p_plus
                          : ((1.0f - wn) * (1.0f + wn)); // p_minus
    f = u01f(tf_bits(k0, k1, e)) < pf;
  }

  // --- draw 3: umin (branch-specific key) only where u && !f (~2.8%)
  bool m = false;
  if (__any_sync(FM, u && !f)) {
    const uint32_t k0 = (br <= 2) ? ((br == 1) ? RK6a : K7Aa)
                                  : ((br == 3) ? K7Ba : K7Ca);
    const uint32_t k1 = (br <= 2) ? ((br == 1) ? RK6b : K7Ab)
                                  : ((br == 3) ? K7Bb : K7Cb);
    m = u01f(tf_bits(k0, k1, e)) < 0.03125f;          // 4/128
  }

  // delta = u * max(f, umin) in {0,1}; applied with sign of the branch.
  // (w +- 0.0f) == w and (w +- 1.0f) matches the single f32 add in the ref.
  float r = w;
  if (u) {
    const float d = (f | m) ? 1.0f : 0.0f;
    r = plus ? (w + d) : (w - d);
  }
  out[e] = r;
}

extern "C" void kernel_launch(void* const* d_in, const int* in_sizes, int n_in,
                              void* d_out, int out_size) {
  (void)in_sizes; (void)n_in; (void)out_size;
  const int*   ispk = (const int*)d_in[0];
  const int*   ospk = (const int*)d_in[1];
  const float* W    = (const float*)d_in[2];
  float*       out  = (float*)d_out;
  modstdp_kernel<<<TOT / 256, 256>>>(ispk, ospk, W, out);
}

// round 5
// speedup vs baseline: 1.6622x; 1.6622x over previous
#include <cuda_runtime.h>
#include <stdint.h>

// ModSTDP: bit-exact jax.random threefry2x32 (partitionable scheme, verified
// rel_err=0.0 in R2) + 4-branch STDP update.
// R5 = R4 resubmit (broker timeouts; kernel has never run).
// Block-level compaction of f/umin draws -> ~1.11 threefry/elem (was 2.5),
// vectorized int4/float4 loads. Target: the ~100us memory floor.

constexpr uint32_t NNEUR = 2048;
constexpr uint32_t NSYN  = 8192;
constexpr uint32_t TOT   = NNEUR * NSYN;   // 2^24

constexpr int BT  = 256;        // threads per block
constexpr int EPT = 8;          // elements per thread (contiguous)
constexpr int BE  = BT * EPT;   // 2048 elements per block

// ---------------- compile-time threefry2x32 (key derivation) ----------------
struct P2 { uint32_t a, b; };
constexpr uint32_t rotl_c(uint32_t x, int r) { return (x << r) | (x >> (32 - r)); }

constexpr P2 tf_c(uint32_t k0, uint32_t k1, uint32_t c0, uint32_t c1) {
  uint32_t k2 = k0 ^ k1 ^ 0x1BD11BDAu;
  uint32_t x0 = c0 + k0, x1 = c1 + k1;
  int RA[4] = {13, 15, 26, 6};
  int RB[4] = {17, 29, 16, 24};
  for (int i = 0; i < 4; i++) { x0 += x1; x1 = rotl_c(x1, RA[i]); x1 ^= x0; }
  x0 += k1; x1 += k2 + 1u;
  for (int i = 0; i < 4; i++) { x0 += x1; x1 = rotl_c(x1, RB[i]); x1 ^= x0; }
  x0 += k2; x1 += k0 + 2u;
  for (int i = 0; i < 4; i++) { x0 += x1; x1 = rotl_c(x1, RA[i]); x1 ^= x0; }
  x0 += k0; x1 += k1 + 3u;
  for (int i = 0; i < 4; i++) { x0 += x1; x1 = rotl_c(x1, RB[i]); x1 ^= x0; }
  x0 += k1; x1 += k2 + 4u;
  for (int i = 0; i < 4; i++) { x0 += x1; x1 = rotl_c(x1, RA[i]); x1 ^= x0; }
  x0 += k2; x1 += k0 + 5u;
  return P2{x0, x1};
}

// master key (0,42); rk[i]=tf((0,42),(0,i)).
// rk0 fplus, rk1 fminus, rk2 ucap, rk3 uminus, rk4 usearch, rk5 ubackoff,
// rk6 umin1; split(rk7,3) -> umin2, umin3, umin4.
constexpr P2 RK7_ = tf_c(0u, 42u, 0u, 7u);
constexpr uint32_t RK0a = tf_c(0u,42u,0u,0u).a, RK0b = tf_c(0u,42u,0u,0u).b;
constexpr uint32_t RK1a = tf_c(0u,42u,0u,1u).a, RK1b = tf_c(0u,42u,0u,1u).b;
constexpr uint32_t RK2a = tf_c(0u,42u,0u,2u).a, RK2b = tf_c(0u,42u,0u,2u).b;
constexpr uint32_t RK3a = tf_c(0u,42u,0u,3u).a, RK3b = tf_c(0u,42u,0u,3u).b;
constexpr uint32_t RK4a = tf_c(0u,42u,0u,4u).a, RK4b = tf_c(0u,42u,0u,4u).b;
constexpr uint32_t RK5a = tf_c(0u,42u,0u,5u).a, RK5b = tf_c(0u,42u,0u,5u).b;
constexpr uint32_t RK6a = tf_c(0u,42u,0u,6u).a, RK6b = tf_c(0u,42u,0u,6u).b;
constexpr uint32_t K7Aa = tf_c(RK7_.a,RK7_.b,0u,0u).a, K7Ab = tf_c(RK7_.a,RK7_.b,0u,0u).b;
constexpr uint32_t K7Ba = tf_c(RK7_.a,RK7_.b,0u,1u).a, K7Bb = tf_c(RK7_.a,RK7_.b,0u,1u).b;
constexpr uint32_t K7Ca = tf_c(RK7_.a,RK7_.b,0u,2u).a, K7Cb = tf_c(RK7_.a,RK7_.b,0u,2u).b;

// u-draw thresholds, pre-shifted: u01(bits) < k/128  <=>  bits < (k/128 * 2^23)<<9
constexpr uint32_t TH_CAP  = 655360u  << 9;  // 10/128 (capture & minus)
constexpr uint32_t TH_SRCH = 65536u   << 9;  // 1/128
constexpr uint32_t TH_BACK = 6291456u << 9;  // 96/128
constexpr uint32_t TH_UMIN = 262144u  << 9;  // 4/128

// ---------------- device threefry ----------------
__device__ __forceinline__ uint32_t tf_bits(uint32_t k0, uint32_t k1, uint32_t e) {
  uint32_t k2 = k0 ^ k1 ^ 0x1BD11BDAu;
  uint32_t x0 = k0;          // hi counter = 0
  uint32_t x1 = e + k1;      // lo counter = e
#define R_(r) { x0 += x1; x1 = __funnelshift_l(x1, x1, (r)); x1 ^= x0; }
  R_(13) R_(15) R_(26) R_(6)
  x0 += k1; x1 += k2 + 1u;
  R_(17) R_(29) R_(16) R_(24)
  x0 += k2; x1 += k0 + 2u;
  R_(13) R_(15) R_(26) R_(6)
  x0 += k0; x1 += k1 + 3u;
  R_(17) R_(29) R_(16) R_(24)
  x0 += k1; x1 += k2 + 4u;
  R_(13) R_(15) R_(26) R_(6)
  x0 += k2; x1 += k0 + 5u;
#undef R_
  return x0 ^ x1;
}

// ---------------- main kernel ----------------
__global__ void __launch_bounds__(BT) modstdp_kernel(
    const int* __restrict__ ispk,     // [8, N, S]
    const int* __restrict__ ospk,     // [8, N]
    const float* __restrict__ W,      // [N, S]
    float* __restrict__ out)          // [N, S]
{
  __shared__ float    sw[BE];                    // clamped weights (8KB)
  __shared__ uint16_t q1[BE];                    // u-survivors: (lidx<<2)|(br-1)
  __shared__ uint16_t q2[BE];                    // u & !f survivors
  __shared__ __align__(8) uint8_t sd[BE];        // delta flag per element (2KB)
  __shared__ int      cnt1, cnt2;

  const uint32_t tid  = threadIdx.x;
  const uint32_t base = blockIdx.x * (uint32_t)BE;
  const uint32_t e0   = base + tid * EPT;        // 8 contiguous elements

  if (tid == 0) { cnt1 = 0; cnt2 = 0; }
  *reinterpret_cast<uint64_t*>(&sd[tid * EPT]) = 0ull;   // zero my 8 flags

  // ---- spike-count sum over T=8 (vectorized int4: 16 LDG.128/thread) ----
  int s[EPT];
#pragma unroll
  for (int i = 0; i < EPT; i++) s[i] = 0;
#pragma unroll
  for (int t = 0; t < 8; t++) {
    const int4* p = reinterpret_cast<const int4*>(ispk + (size_t)t * TOT + e0);
    int4 a = __ldg(p), b = __ldg(p + 1);
    s[0] += a.x; s[1] += a.y; s[2] += a.z; s[3] += a.w;
    s[4] += b.x; s[5] += b.y; s[6] += b.z; s[7] += b.w;
  }

  // ---- out-spike sum: neuron is block-uniform (BE=2048 divides S=8192) ----
  const uint32_t n = base >> 13;
  int so = 0;
#pragma unroll
  for (int t = 0; t < 8; t++) so += __ldg(ospk + t * NNEUR + n);
  const bool ouf = so > 0;                       // out fired
  // it <= ot  <=>  8-s <= 8-so  <=>  s >= so

  // ---- weights (2x float4), clamp, stage to smem ----
  float w[EPT];
  {
    const float4* p = reinterpret_cast<const float4*>(W + e0);
    float4 a = __ldg(p), b = __ldg(p + 1);
    w[0]=a.x; w[1]=a.y; w[2]=a.z; w[3]=a.w;
    w[4]=b.x; w[5]=b.y; w[6]=b.z; w[7]=b.w;
  }
#pragma unroll
  for (int i = 0; i < EPT; i++) {
    w[i] = fminf(fmaxf(w[i], 0.0f), 8.0f);
    sw[tid * EPT + i] = w[i];
  }
  __syncthreads();   // sd zeroed + sw visible (also covers cnt init)

  // ---- phase 1: mandatory u-draw per element; push survivors ----
  uint32_t umask = 0, plusmask = 0;
#pragma unroll
  for (int i = 0; i < EPT; i++) {
    const bool inf = s[i] > 0;
    // br: 1 capture(+), 2 minus(-), 3 search(+), 4 backoff(-), 0 none
    const int br = (inf & ouf) ? ((s[i] >= so) ? 1 : 2)
                               : (inf ? 3 : (ouf ? 4 : 0));
    const bool plus = (br == 1) | (br == 3);
    plusmask |= (uint32_t)plus << i;

    const uint32_t k0 = (br <= 2) ? ((br == 1) ? RK2a : RK3a)
                                  : ((br == 3) ? RK4a : RK5a);
    const uint32_t k1 = (br <= 2) ? ((br == 1) ? RK2b : RK3b)
                                  : ((br == 3) ? RK4b : RK5b);
    const uint32_t th = (br <= 2) ? TH_CAP
                                  : ((br == 3) ? TH_SRCH : TH_BACK);
    const uint32_t bits = tf_bits(k0, k1, e0 + i);
    if ((bits < th) & (br != 0)) {
      umask |= 1u << i;
      const int slot = atomicAdd(&cnt1, 1);      // warp-aggregated by ptxas
      q1[slot] = (uint16_t)(((tid * EPT + i) << 2) | (br - 1));
    }
  }
  __syncthreads();

  // ---- phase 2: f-draw only for u-survivors (~8%) ----
  const int c1 = cnt1;
  for (int k = tid; k < c1; k += BT) {
    const uint32_t ent  = q1[k];
    const uint32_t lidx = ent >> 2;
    const uint32_t brm  = ent & 3;               // br-1
    const bool plus = (brm == 0) | (brm == 2);
    const float w_  = sw[lidx];
    const float wn  = w_ * 0.125f;
    const float pf  = plus ? (wn * (2.0f - wn)) : ((1.0f - wn) * (1.0f + wn));
    const uint32_t bits = tf_bits(plus ? RK0a : RK1a, plus ? RK0b : RK1b,
                                  base + lidx);
    const float uu = (float)(bits >> 9) * 0x1p-23f;   // == JAX uniform exactly
    if (uu < pf) {
      sd[lidx] = 1;
    } else {
      const int slot = atomicAdd(&cnt2, 1);
      q2[slot] = (uint16_t)ent;
    }
  }
  __syncthreads();

  // ---- phase 3: umin-draw only for u & !f survivors (~2.6%) ----
  const int c2 = cnt2;
  for (int k = tid; k < c2; k += BT) {
    const uint32_t ent  = q2[k];
    const uint32_t lidx = ent >> 2;
    const uint32_t brm  = ent & 3;
    // umin keys: br1->rk6, br2->k7a, br3->k7b, br4->k7c
    const uint32_t k0 = (brm <= 1) ? ((brm == 0) ? RK6a : K7Aa)
                                   : ((brm == 2) ? K7Ba : K7Ca);
    const uint32_t k1 = (brm <= 1) ? ((brm == 0) ? RK6b : K7Ab)
                                   : ((brm == 2) ? K7Bb : K7Cb);
    if (tf_bits(k0, k1, base + lidx) < TH_UMIN) sd[lidx] = 1;
  }
  __syncthreads();

  // ---- final: apply deltas, vectorized store ----
  float r[EPT];
#pragma unroll
  for (int i = 0; i < EPT; i++) {
    const float d = (umask >> i & 1u) ? (float)sd[tid * EPT + i] : 0.0f;
    r[i] = (plusmask >> i & 1u) ? (w[i] + d) : (w[i] - d);
  }
  float4* po = reinterpret_cast<float4*>(out + e0);
  po[0] = make_float4(r[0], r[1], r[2], r[3]);
  po[1] = make_float4(r[4], r[5], r[6], r[7]);
}

extern "C" void kernel_launch(void* const* d_in, const int* in_sizes, int n_in,
                              void* d_out, int out_size) {
  (void)in_sizes; (void)n_in; (void)out_size;
  const int*   ispk = (const int*)d_in[0];
  const int*   ospk = (const int*)d_in[1];
  const float* W    = (const float*)d_in[2];
  float*       out  = (float*)d_out;
  modstdp_kernel<<<TOT / BE, BT>>>(ispk, ospk, W, out);
}